// round 11
// baseline (speedup 1.0000x reference)
#include <cuda_runtime.h>
#include <cuda.h>
#include <stdint.h>
#include <math.h>

#define NTOK 16384
#define HD   4096
#define NE   64
#define NP   6
#define TK   8

#define CWARPS   8
#define NTHREADS ((CWARPS + 1) * 32)   // 288
#define PROD_WARP CWARPS
#define TPW      4
#define UNIT_TOK (CWARPS * TPW)        // 32
#define NUNITS   (NTOK / UNIT_TOK)     // 512
#define CHUNK_C  256                   // columns per chunk
#define NCHUNK   (HD / CHUNK_C)        // 16
#define STAGE_BYTES (UNIT_TOK * CHUNK_C * 4)  // 32768
#define STAGES   3
#define GRID     296

// smem byte offsets
#define XS_OFF    0
#define CENT_OFF  (STAGES * STAGE_BYTES)          // 98304
#define CENTN_OFF (CENT_OFF + NE * NP * 4)
#define CPART_OFF (CENTN_OFF + NE * 4)
#define CVEC_OFF  (CPART_OFF + CWARPS * NP * 4)
#define UID_OFF   (CVEC_OFF + 32)
#define MBAR_OFF  (UID_OFF + 16)
#define SMEM_BYTES (MBAR_OFF + 64)               // ~100.4 KB -> 2 CTAs/SM

__device__ unsigned g_unit_ctr;

#define FMA2(acc, a, b) \
    asm("fma.rn.f32x2 %0, %1, %2, %0;" : "+l"(acc) : "l"(a), "l"(b))
#define ADD2(d, a, b) \
    asm("add.rn.f32x2 %0, %1, %2;" : "=l"(d) : "l"(a), "l"(b))

__device__ __forceinline__ uint32_t smem_u32(const void* p) {
    uint32_t a;
    asm("{ .reg .u64 t; cvta.to.shared.u64 t, %1; cvt.u32.u64 %0, t; }" : "=r"(a) : "l"(p));
    return a;
}

#define MBAR_INIT(addr, cnt) \
    asm volatile("mbarrier.init.shared.b64 [%0], %1;" :: "r"(addr), "r"(cnt) : "memory")
#define MBAR_EXPECT_TX(addr, bytes) \
    asm volatile("mbarrier.arrive.expect_tx.shared.b64 _, [%0], %1;" :: "r"(addr), "r"(bytes) : "memory")
#define MBAR_ARRIVE(addr) \
    asm volatile("mbarrier.arrive.shared.b64 _, [%0];" :: "r"(addr) : "memory")
#define MBAR_WAIT(addr, parity) do {                                             \
    asm volatile("{\n\t.reg .pred P;\n"                                          \
        "W_%=:\n\tmbarrier.try_wait.parity.acquire.cta.shared::cta.b64 P, [%0], %1, 0x989680;\n" \
        "\t@P bra D_%=;\n\tbra W_%=;\nD_%=:\n\t}"                                \
        :: "r"(addr), "r"(parity) : "memory"); } while (0)

__device__ __forceinline__ void tma2d(uint32_t dst, const CUtensorMap* m,
                                      int cx, int cy, uint32_t mbar) {
    asm volatile(
        "cp.async.bulk.tensor.2d.shared::cta.global.tile.mbarrier::complete_tx::bytes "
        "[%0], [%1, {%2, %3}], [%4];"
        :: "r"(dst), "l"(m), "r"(cx), "r"(cy), "r"(mbar) : "memory");
}

__global__ void reset_ctr_kernel() { g_unit_ctr = 0u; }

__global__ void __launch_bounds__(NTHREADS, 2)
kdtree_router_kernel(const float* __restrict__ mean,
                     const float* __restrict__ comp,
                     const float* __restrict__ cent,
                     float* __restrict__ out,
                     const __grid_constant__ CUtensorMap tmap)
{
    extern __shared__ __align__(1024) char smem_c[];
    float* cent_s  = (float*)(smem_c + CENT_OFF);
    float* centn_s = (float*)(smem_c + CENTN_OFF);
    float* cpart   = (float*)(smem_c + CPART_OFF);
    float* cvec    = (float*)(smem_c + CVEC_OFF);
    unsigned* uid  = (unsigned*)(smem_c + UID_OFF);
    const uint32_t mb = smem_u32(smem_c + MBAR_OFF);
    const uint32_t xs = smem_u32(smem_c + XS_OFF);

    const int tid  = threadIdx.x;
    const int lane = tid & 31;
    const int warp = tid >> 5;

    if (tid == 0) {
        #pragma unroll
        for (int s = 0; s < STAGES; s++) {
            MBAR_INIT(mb + s * 8, 1);               // full
            MBAR_INIT(mb + 24 + s * 8, CWARPS);     // empty
        }
    }
    for (int i = tid; i < NE * NP; i += NTHREADS) cent_s[i] = cent[i];
    __syncthreads();

    // ---------- per-CTA prologue: cvec[p] = mean . comp[p]; centroid norms ----------
    if (warp < CWARPS) {
        float a[NP] = {0.f, 0.f, 0.f, 0.f, 0.f, 0.f};
        #pragma unroll
        for (int j = 0; j < HD / (CWARPS * 32); j++) {
            int h = warp * (HD / CWARPS) + lane + j * 32;
            float m = __ldg(mean + h);
            #pragma unroll
            for (int p = 0; p < NP; p++)
                a[p] += m * __ldg(comp + p * HD + h);
        }
        #pragma unroll
        for (int o = 16; o > 0; o >>= 1)
            #pragma unroll
            for (int p = 0; p < NP; p++)
                a[p] += __shfl_xor_sync(0xffffffffu, a[p], o);
        if (lane == 0)
            #pragma unroll
            for (int p = 0; p < NP; p++) cpart[warp * NP + p] = a[p];
        if (tid < NE) {
            float s = 0.f;
            #pragma unroll
            for (int p = 0; p < NP; p++) { float c = cent_s[tid*NP + p]; s += c * c; }
            centn_s[tid] = s;
        }
    }
    __syncthreads();
    if (tid < NP) {
        float s = 0.f;
        #pragma unroll
        for (int w = 0; w < CWARPS; w++) s += cpart[w * NP + tid];
        cvec[tid] = s;
    }
    __syncthreads();

    if (warp == PROD_WARP) {
        // ======================= producer =======================
        if (lane == 0) {
            int s = 0, f = 0;
            for (;;) {
                unsigned un = atomicAdd(&g_unit_ctr, 1u);
                if (un >= NUNITS) break;
                #pragma unroll 1
                for (int ci = 0; ci < NCHUNK; ci++) {
                    if (f >= 1) MBAR_WAIT(mb + 24 + s * 8, (f & 1) ^ 1);
                    uid[s] = un * 16 + ci;
                    MBAR_EXPECT_TX(mb + s * 8, (uint32_t)STAGE_BYTES);
                    tma2d(xs + s * STAGE_BYTES, &tmap,
                          ci * CHUNK_C, (int)(un * UNIT_TOK), mb + s * 8);
                    if (++s == STAGES) { s = 0; f++; }
                }
            }
            if (f >= 1) MBAR_WAIT(mb + 24 + s * 8, (f & 1) ^ 1);
            uid[s] = 0xFFFFFFFFu;
            MBAR_ARRIVE(mb + s * 8);
        }
        return;
    }

    // ======================= consumers: 8 warps x 4 tokens, reg accumulation =======================
    float mpj[NP];
    #pragma unroll
    for (int p = 0; p < NP; p++) mpj[p] = cvec[p];

    float* out_idx = out;
    float* out_tp  = out + (size_t)NTOK * TK;
    float* out_pr  = out + 2 * (size_t)NTOK * TK;

    unsigned long long acc[TPW][NP];
    int s = 0, f = 0;
    for (;;) {
        MBAR_WAIT(mb + s * 8, f & 1);
        unsigned v = uid[s];
        if (v == 0xFFFFFFFFu) break;
        const int ci = (int)(v & 15u);
        const unsigned unit = v >> 4;

        if (ci == 0) {
            #pragma unroll
            for (int t = 0; t < TPW; t++)
                #pragma unroll
                for (int p = 0; p < NP; p++) acc[t][p] = 0ull;
        }

        // comp chunk -> regs (L2/L1 resident; identical lines across warps)
        ulonglong2 cpa[NP], cpb[NP];
        #pragma unroll
        for (int p = 0; p < NP; p++) {
            const ulonglong2* cb = (const ulonglong2*)(comp + (size_t)p * HD + ci * CHUNK_C);
            cpa[p] = __ldg(cb + lane);
            cpb[p] = __ldg(cb + 32 + lane);
        }

        // accumulate 4 tokens' slices from stage
        #pragma unroll
        for (int t = 0; t < TPW; t++) {
            const ulonglong2* xr = (const ulonglong2*)
                (smem_c + XS_OFF + s * STAGE_BYTES + (warp * TPW + t) * (CHUNK_C * 4));
            ulonglong2 xa = xr[lane];
            ulonglong2 xb = xr[32 + lane];
            #pragma unroll
            for (int p = 0; p < NP; p++) {
                FMA2(acc[t][p], xa.x, cpa[p].x); FMA2(acc[t][p], xa.y, cpa[p].y);
                FMA2(acc[t][p], xb.x, cpb[p].x); FMA2(acc[t][p], xb.y, cpb[p].y);
            }
        }
        __syncwarp();
        if (lane == 0) MBAR_ARRIVE(mb + 24 + s * 8);
        if (++s == STAGES) { s = 0; f ^= 1; }

        if (ci == NCHUNK - 1) {
            // ---- unit epilogue: this warp's 4 tokens (no cross-warp sync) ----
            #pragma unroll 1
            for (int t = 0; t < TPW; t++) {
                const unsigned tok = unit * UNIT_TOK + warp * TPW + t;

                // packed butterfly reduce: 3 ull lanes-sums -> all lanes
                unsigned long long u[3];
                #pragma unroll
                for (int j = 0; j < 3; j++) {
                    float f0 = __uint_as_float((unsigned)(acc[t][2*j]   & 0xffffffffull)) +
                               __uint_as_float((unsigned)(acc[t][2*j]   >> 32));
                    float f1 = __uint_as_float((unsigned)(acc[t][2*j+1] & 0xffffffffull)) +
                               __uint_as_float((unsigned)(acc[t][2*j+1] >> 32));
                    u[j] = ((unsigned long long)__float_as_uint(f1) << 32) | __float_as_uint(f0);
                }
                #pragma unroll
                for (int o = 16; o >= 1; o >>= 1)
                    #pragma unroll
                    for (int j = 0; j < 3; j++) {
                        unsigned long long w = __shfl_xor_sync(0xffffffffu, u[j], o);
                        ADD2(u[j], u[j], w);
                    }
                float pr[NP];
                #pragma unroll
                for (int j = 0; j < 3; j++) {
                    pr[2*j]   = __uint_as_float((unsigned)(u[j] & 0xffffffffull)) - mpj[2*j];
                    pr[2*j+1] = __uint_as_float((unsigned)(u[j] >> 32))           - mpj[2*j+1];
                }

                float pn = 0.f;
                #pragma unroll
                for (int p = 0; p < NP; p++) pn += pr[p] * pr[p];

                const int e0 = lane, e1 = lane + 32;
                float dot0 = 0.f, dot1 = 0.f;
                #pragma unroll
                for (int p = 0; p < NP; p++) {
                    dot0 += pr[p] * cent_s[e0*NP + p];
                    dot1 += pr[p] * cent_s[e1*NP + p];
                }
                float d20 = pn - 2.f*dot0 + centn_s[e0];
                float d21 = pn - 2.f*dot1 + centn_s[e1];
                float s0 = -sqrtf(fmaxf(d20, 0.f));
                float s1 = -sqrtf(fmaxf(d21, 0.f));

                float m = fmaxf(s0, s1);
                #pragma unroll
                for (int o = 16; o > 0; o >>= 1)
                    m = fmaxf(m, __shfl_xor_sync(0xffffffffu, m, o));
                float ex0 = expf(s0 - m);
                float ex1 = expf(s1 - m);
                float sum = ex0 + ex1;
                #pragma unroll
                for (int o = 16; o > 0; o >>= 1)
                    sum += __shfl_xor_sync(0xffffffffu, sum, o);
                float p0 = ex0 / sum;
                float p1 = ex1 / sum;

                out_pr[(size_t)tok*NE + e0] = p0;
                out_pr[(size_t)tok*NE + e1] = p1;

                // top-8 via 8-round warp argmax; tie-break = lower index
                unsigned long long k0 = ((unsigned long long)__float_as_uint(p0) << 32) | (unsigned)(NE-1 - e0);
                unsigned long long k1 = ((unsigned long long)__float_as_uint(p1) << 32) | (unsigned)(NE-1 - e1);
                float tsum = 0.f, myp = 0.f;
                int myi = 0;
                #pragma unroll
                for (int r = 0; r < TK; r++) {
                    unsigned long long b = (k0 > k1) ? k0 : k1;
                    #pragma unroll
                    for (int o = 16; o > 0; o >>= 1) {
                        unsigned long long w = __shfl_xor_sync(0xffffffffu, b, o);
                        if (w > b) b = w;
                    }
                    int idx = NE-1 - (int)(b & 0xffull);
                    float pv = __uint_as_float((unsigned)(b >> 32));
                    tsum += pv;
                    if (lane == r) { myp = pv; myi = idx; }
                    if (idx == e0) k0 = 0ull;
                    if (idx == e1) k1 = 0ull;
                }
                if (lane < TK) {
                    out_idx[(size_t)tok*TK + lane] = (float)myi;
                    out_tp [(size_t)tok*TK + lane] = myp / tsum;
                }
            }
        }
    }
}

typedef CUresult (*EncodeTiledFn)(
    CUtensorMap*, CUtensorMapDataType, cuuint32_t, void*,
    const cuuint64_t*, const cuuint64_t*, const cuuint32_t*, const cuuint32_t*,
    CUtensorMapInterleave, CUtensorMapSwizzle, CUtensorMapL2promotion,
    CUtensorMapFloatOOBfill);

extern "C" void kernel_launch(void* const* d_in, const int* in_sizes, int n_in,
                              void* d_out, int out_size)
{
    const float* x    = (const float*)d_in[0];
    const float* mean = (const float*)d_in[1];
    const float* comp = (const float*)d_in[2];
    const float* cent = (const float*)d_in[3];
    float* out = (float*)d_out;

    void* fn = nullptr;
    cudaDriverEntryPointQueryResult qres;
    cudaGetDriverEntryPointByVersion("cuTensorMapEncodeTiled", &fn, 12000,
                                     cudaEnableDefault, &qres);

    CUtensorMap tmap;
    cuuint64_t gdim[2] = {HD, NTOK};
    cuuint64_t gstr[1] = {HD * sizeof(float)};
    cuuint32_t box[2]  = {CHUNK_C, UNIT_TOK};
    cuuint32_t est[2]  = {1, 1};
    ((EncodeTiledFn)fn)(&tmap, CU_TENSOR_MAP_DATA_TYPE_FLOAT32, 2, (void*)x,
                        gdim, gstr, box, est,
                        CU_TENSOR_MAP_INTERLEAVE_NONE, CU_TENSOR_MAP_SWIZZLE_NONE,
                        CU_TENSOR_MAP_L2_PROMOTION_L2_128B,
                        CU_TENSOR_MAP_FLOAT_OOB_FILL_NONE);

    reset_ctr_kernel<<<1, 1>>>();
    cudaFuncSetAttribute(kdtree_router_kernel,
                         cudaFuncAttributeMaxDynamicSharedMemorySize, SMEM_BYTES);
    kdtree_router_kernel<<<GRID, NTHREADS, SMEM_BYTES>>>(mean, comp, cent, out, tmap);
}

// round 12
// speedup vs baseline: 1.9551x; 1.9551x over previous
#include <cuda_runtime.h>
#include <stdint.h>
#include <math.h>

#define NTOK 16384
#define HD   4096
#define NE   64
#define NP   6
#define TK   8

#define CWARPS   16
#define NTHREADS ((CWARPS + 1) * 32)    // 544
#define PROD_WARP CWARPS
#define SLICE    (HD / CWARPS)          // 256

#define UNIT_TOK  16
#define NUNITS    (NTOK / UNIT_TOK)     // 1024
#define STAGE_TOK 2
#define STAGE_BYTES (STAGE_TOK * HD * 4)   // 32768
#define NSPLIT    4                        // concurrent copies per stage
#define SPLIT_BYTES (STAGE_BYTES / NSPLIT) // 8192
#define STAGES    4
#define CPU       (UNIT_TOK / STAGE_TOK)   // 8 chunks per unit
#define GRID      148

// smem byte offsets
#define XS_OFF    0
#define PART_OFF  (STAGES * STAGE_BYTES)                 // 131072
#define PART_SZ   ((UNIT_TOK + 1) * NP * 32 * 4)         // 13056
#define CENT_OFF  (PART_OFF + PART_SZ)
#define CENTN_OFF (CENT_OFF + NE * NP * 4)
#define UID_OFF   (CENTN_OFF + NE * 4)
#define MBAR_OFF  (UID_OFF + 16)
#define SMEM_BYTES (MBAR_OFF + 64)

__device__ unsigned g_unit_ctr;

#define FMA2(acc, a, b) \
    asm("fma.rn.f32x2 %0, %1, %2, %0;" : "+l"(acc) : "l"(a), "l"(b))
#define ADD2(d, a, b) \
    asm("add.rn.f32x2 %0, %1, %2;" : "=l"(d) : "l"(a), "l"(b))

__device__ __forceinline__ uint32_t smem_u32(const void* p) {
    uint32_t a;
    asm("{ .reg .u64 t; cvta.to.shared.u64 t, %1; cvt.u32.u64 %0, t; }" : "=r"(a) : "l"(p));
    return a;
}

#define MBAR_INIT(addr, cnt) \
    asm volatile("mbarrier.init.shared.b64 [%0], %1;" :: "r"(addr), "r"(cnt) : "memory")
#define MBAR_EXPECT_TX(addr, bytes) \
    asm volatile("mbarrier.arrive.expect_tx.shared.b64 _, [%0], %1;" :: "r"(addr), "r"(bytes) : "memory")
#define MBAR_ARRIVE(addr) \
    asm volatile("mbarrier.arrive.shared.b64 _, [%0];" :: "r"(addr) : "memory")
#define MBAR_WAIT(addr, parity) do {                                             \
    asm volatile("{\n\t.reg .pred P;\n"                                          \
        "W_%=:\n\tmbarrier.try_wait.parity.acquire.cta.shared::cta.b64 P, [%0], %1, 0x989680;\n" \
        "\t@P bra D_%=;\n\tbra W_%=;\nD_%=:\n\t}"                                \
        :: "r"(addr), "r"(parity) : "memory"); } while (0)

__device__ __forceinline__ void bulk_g2s(uint32_t dst, const void* src,
                                         uint32_t bytes, uint32_t mbar) {
    asm volatile(
        "cp.async.bulk.shared::cta.global.mbarrier::complete_tx::bytes "
        "[%0], [%1], %2, [%3];"
        :: "r"(dst), "l"(src), "r"(bytes), "r"(mbar) : "memory");
}

#define CBAR() asm volatile("bar.sync 1, 512;" ::: "memory")

// compute one token's projection partial (uses cA,cB,part,warp,lane from scope)
#define TOKEN_COMPUTE(xa, xb, LTOK) do {                                              \
    unsigned long long acc_[NP];                                                      \
    _Pragma("unroll")                                                                 \
    for (int p_ = 0; p_ < NP; p_++) {                                                 \
        acc_[p_] = 0ull;                                                              \
        FMA2(acc_[p_], (xa).x, cA[p_].x); FMA2(acc_[p_], (xa).y, cA[p_].y);           \
        FMA2(acc_[p_], (xb).x, cB[p_].x); FMA2(acc_[p_], (xb).y, cB[p_].y);           \
    }                                                                                 \
    unsigned long long u_[3];                                                         \
    _Pragma("unroll")                                                                 \
    for (int j_ = 0; j_ < 3; j_++) {                                                  \
        float f0_ = __uint_as_float((unsigned)(acc_[2*j_]   & 0xffffffffull)) +       \
                    __uint_as_float((unsigned)(acc_[2*j_]   >> 32));                  \
        float f1_ = __uint_as_float((unsigned)(acc_[2*j_+1] & 0xffffffffull)) +       \
                    __uint_as_float((unsigned)(acc_[2*j_+1] >> 32));                  \
        u_[j_] = ((unsigned long long)__float_as_uint(f1_) << 32) | __float_as_uint(f0_); \
    }                                                                                 \
    _Pragma("unroll")                                                                 \
    for (int o_ = 16; o_ >= 2; o_ >>= 1)                                              \
        _Pragma("unroll")                                                             \
        for (int j_ = 0; j_ < 3; j_++) {                                              \
            unsigned long long v_ = __shfl_xor_sync(0xffffffffu, u_[j_], o_);         \
            ADD2(u_[j_], u_[j_], v_);                                                 \
        }                                                                             \
    if (lane < 2) {                                                                   \
        int slot_ = warp * 2 + lane;                                                  \
        _Pragma("unroll")                                                             \
        for (int j_ = 0; j_ < 3; j_++) {                                              \
            part[((LTOK)*NP + 2*j_  )*32 + slot_] = __uint_as_float((unsigned)(u_[j_] & 0xffffffffull)); \
            part[((LTOK)*NP + 2*j_+1)*32 + slot_] = __uint_as_float((unsigned)(u_[j_] >> 32));           \
        }                                                                             \
    }                                                                                 \
} while (0)

__global__ void reset_ctr_kernel() { g_unit_ctr = 0u; }

__global__ void __launch_bounds__(NTHREADS, 1)
kdtree_router_kernel(const float* __restrict__ x,
                     const float* __restrict__ mean,
                     const float* __restrict__ comp,
                     const float* __restrict__ cent,
                     float* __restrict__ out)
{
    extern __shared__ __align__(1024) char smem_c[];
    float* part    = (float*)(smem_c + PART_OFF);
    float* cent_s  = (float*)(smem_c + CENT_OFF);
    float* centn_s = (float*)(smem_c + CENTN_OFF);
    unsigned* uid  = (unsigned*)(smem_c + UID_OFF);
    const uint32_t mb = smem_u32(smem_c + MBAR_OFF);
    const uint32_t xs = smem_u32(smem_c + XS_OFF);

    const int tid  = threadIdx.x;
    const int lane = tid & 31;
    const int warp = tid >> 5;

    if (tid == 0) {
        #pragma unroll
        for (int s = 0; s < STAGES; s++) {
            MBAR_INIT(mb + s * 8, 1);               // full: expect_tx arrive
            MBAR_INIT(mb + 32 + s * 8, CWARPS);     // empty: 16 warp arrivals
        }
    }
    for (int i = tid; i < NE * NP; i += NTHREADS) cent_s[i] = cent[i];
    __syncthreads();

    // ---------- per-CTA prologue ----------
    ulonglong2 cA[NP], cB[NP];
    if (warp < CWARPS) {
        const ulonglong2* cp0 = (const ulonglong2*)(comp + warp * SLICE);
        #pragma unroll
        for (int p = 0; p < NP; p++) {
            cA[p] = cp0[(size_t)p * (HD/4) + lane];
            cB[p] = cp0[(size_t)p * (HD/4) + lane + 32];
        }
        const ulonglong2* mp = (const ulonglong2*)(mean + warp * SLICE);
        ulonglong2 ma = mp[lane], mbv = mp[lane + 32];
        TOKEN_COMPUTE(ma, mbv, UNIT_TOK);   // mean proj partials -> row 16
        if (tid < NE) {
            float s = 0.f;
            #pragma unroll
            for (int p = 0; p < NP; p++) { float c = cent_s[tid*NP + p]; s += c * c; }
            centn_s[tid] = s;
        }
    }
    __syncthreads();

    if (warp == PROD_WARP) {
        // ======== producer: 4 lanes issue 4 concurrent 8 KB copies per stage ========
        unsigned pc = 0;
        for (;;) {
            unsigned un;
            if (lane == 0) un = atomicAdd(&g_unit_ctr, 1u);
            un = __shfl_sync(0xffffffffu, un, 0);
            if (un >= NUNITS) break;
            const char* ubase = (const char*)x + (size_t)un * UNIT_TOK * HD * 4;
            #pragma unroll 1
            for (int ci = 0; ci < CPU; ci++) {
                int s = (int)(pc & (STAGES - 1));
                unsigned up = pc >> 2;
                if (lane < NSPLIT && pc >= STAGES)
                    MBAR_WAIT(mb + 32 + s * 8, (up & 1) ^ 1);
                __syncwarp();
                if (lane == 0) {
                    uid[s] = un * UNIT_TOK + ci * STAGE_TOK;
                    MBAR_EXPECT_TX(mb + s * 8, (uint32_t)STAGE_BYTES);
                }
                __syncwarp();
                if (lane < NSPLIT)
                    bulk_g2s(xs + s * STAGE_BYTES + lane * SPLIT_BYTES,
                             ubase + (size_t)ci * STAGE_BYTES + lane * SPLIT_BYTES,
                             SPLIT_BYTES, mb + s * 8);
                pc++;
            }
        }
        // sentinel
        {
            int s = (int)(pc & (STAGES - 1));
            unsigned up = pc >> 2;
            if (lane == 0) {
                if (pc >= STAGES) MBAR_WAIT(mb + 32 + s * 8, (up & 1) ^ 1);
                uid[s] = 0xFFFFFFFFu;
                MBAR_ARRIVE(mb + s * 8);
            }
        }
        return;
    }

    // ======================= consumers =======================
    float mpj[NP];
    #pragma unroll
    for (int p = 0; p < NP; p++) {
        float v = part[(UNIT_TOK*NP + p)*32 + lane];
        #pragma unroll
        for (int o = 16; o > 0; o >>= 1)
            v += __shfl_xor_sync(0xffffffffu, v, o);
        mpj[p] = v;
    }

    float* out_idx = out;
    float* out_tp  = out + (size_t)NTOK * TK;
    float* out_pr  = out + 2 * (size_t)NTOK * TK;

    unsigned pc = 0;
    for (;;) {
        int s = (int)(pc & (STAGES - 1));
        unsigned up = pc >> 2;
        MBAR_WAIT(mb + s * 8, up & 1);
        unsigned tokbase = uid[s];
        if (tokbase == 0xFFFFFFFFu) break;

        #pragma unroll
        for (int t = 0; t < STAGE_TOK; t++) {
            const ulonglong2* xp = (const ulonglong2*)
                (smem_c + XS_OFF + s * STAGE_BYTES + t * (HD*4) + warp * (SLICE*4));
            ulonglong2 xa = xp[lane];
            ulonglong2 xb = xp[lane + 32];
            int ltok = (int)(tokbase & 15u) + t;
            TOKEN_COMPUTE(xa, xb, ltok);
        }
        __syncwarp();
        if (lane == 0) MBAR_ARRIVE(mb + 32 + s * 8);
        pc++;

        if ((tokbase & 15u) == (UNIT_TOK - STAGE_TOK)) {
            // ---- unit complete -> epilogue: warp w handles token w ----
            CBAR();
            const unsigned tok = (tokbase & ~15u) + warp;

            float pr[NP];
            #pragma unroll
            for (int p = 0; p < NP; p++) {
                float v = part[(warp*NP + p)*32 + lane];
                #pragma unroll
                for (int o = 16; o > 0; o >>= 1)
                    v += __shfl_xor_sync(0xffffffffu, v, o);
                pr[p] = v - mpj[p];
            }
            float pn = 0.f;
            #pragma unroll
            for (int p = 0; p < NP; p++) pn += pr[p] * pr[p];

            const int e0 = lane, e1 = lane + 32;
            float dot0 = 0.f, dot1 = 0.f;
            #pragma unroll
            for (int p = 0; p < NP; p++) {
                dot0 += pr[p] * cent_s[e0*NP + p];
                dot1 += pr[p] * cent_s[e1*NP + p];
            }
            float d20 = pn - 2.f*dot0 + centn_s[e0];
            float d21 = pn - 2.f*dot1 + centn_s[e1];
            float s0 = -sqrtf(fmaxf(d20, 0.f));
            float s1 = -sqrtf(fmaxf(d21, 0.f));

            float m = fmaxf(s0, s1);
            #pragma unroll
            for (int o = 16; o > 0; o >>= 1)
                m = fmaxf(m, __shfl_xor_sync(0xffffffffu, m, o));
            float ex0 = expf(s0 - m);
            float ex1 = expf(s1 - m);
            float sum = ex0 + ex1;
            #pragma unroll
            for (int o = 16; o > 0; o >>= 1)
                sum += __shfl_xor_sync(0xffffffffu, sum, o);
            float p0 = ex0 / sum;
            float p1 = ex1 / sum;

            out_pr[(size_t)tok*NE + e0] = p0;
            out_pr[(size_t)tok*NE + e1] = p1;

            // top-8 via 8-round warp argmax; tie-break = lower index
            unsigned long long k0 = ((unsigned long long)__float_as_uint(p0) << 32) | (unsigned)(NE-1 - e0);
            unsigned long long k1 = ((unsigned long long)__float_as_uint(p1) << 32) | (unsigned)(NE-1 - e1);
            float tsum = 0.f, myp = 0.f;
            int myi = 0;
            #pragma unroll
            for (int r = 0; r < TK; r++) {
                unsigned long long b = (k0 > k1) ? k0 : k1;
                #pragma unroll
                for (int o = 16; o > 0; o >>= 1) {
                    unsigned long long v = __shfl_xor_sync(0xffffffffu, b, o);
                    if (v > b) b = v;
                }
                int idx = NE-1 - (int)(b & 0xffull);
                float pv = __uint_as_float((unsigned)(b >> 32));
                tsum += pv;
                if (lane == r) { myp = pv; myi = idx; }
                if (idx == e0) k0 = 0ull;
                if (idx == e1) k1 = 0ull;
            }
            if (lane < TK) {
                out_idx[(size_t)tok*TK + lane] = (float)myi;
                out_tp [(size_t)tok*TK + lane] = myp / tsum;
            }
            CBAR();   // protect part[] before next unit overwrites
        }
    }
}

extern "C" void kernel_launch(void* const* d_in, const int* in_sizes, int n_in,
                              void* d_out, int out_size)
{
    const float* x    = (const float*)d_in[0];
    const float* mean = (const float*)d_in[1];
    const float* comp = (const float*)d_in[2];
    const float* cent = (const float*)d_in[3];
    float* out = (float*)d_out;

    reset_ctr_kernel<<<1, 1>>>();
    cudaFuncSetAttribute(kdtree_router_kernel,
                         cudaFuncAttributeMaxDynamicSharedMemorySize, SMEM_BYTES);
    kdtree_router_kernel<<<GRID, NTHREADS, SMEM_BYTES>>>(x, mean, comp, cent, out);
}